// round 12
// baseline (speedup 1.0000x reference)
#include <cuda_runtime.h>
#include <math.h>
#include <stdint.h>

// ---------------- problem constants ----------------
#define DIM     768
#define HEADS   12
#define DH      64
#define WIN     14
#define NW      196          // WIN*WIN
#define BATCH   8
#define H0      64
#define W0      64
#define NTOK    4096         // H0*W0
#define NWIN_D  5            // windows per spatial dim (70/14)
#define NWIN_B  25           // windows per batch image
#define NWINTOT 200          // BATCH * NWIN_B
#define MWIN    (NWINTOT*NW) // 39200 windowed tokens
#define MTOK    (BATCH*NTOK) // 32768 real tokens
#define MLP_H   3072
#define QKV_N   (3*DIM)      // 2304
#define SCALE   0.125f
#define EPS     1e-5f

// ---------------- scratch (static device globals; no allocations) ----------------
__device__ float g_xw[(size_t)MWIN * DIM];
__device__ float g_qkv[(size_t)MWIN * QKV_N];
__device__ float g_attnout[(size_t)MWIN * DIM];
__device__ float g_x1[(size_t)MTOK * DIM];
__device__ float g_ln2[(size_t)MTOK * DIM];
__device__ float g_mlp[(size_t)MTOK * MLP_H];

// ---------------- block reduction ----------------
__device__ __forceinline__ float block_reduce_sum_256(float v) {
    __shared__ float red[8];
    int lane = threadIdx.x & 31, wid = threadIdx.x >> 5;
#pragma unroll
    for (int o = 16; o; o >>= 1) v += __shfl_xor_sync(0xffffffffu, v, o);
    __syncthreads();
    if (lane == 0) red[wid] = v;
    __syncthreads();
    float s = red[0];
#pragma unroll
    for (int i = 1; i < 8; i++) s += red[i];
    return s;
}

// ---------------- LN1 + window partition (pads -> zero rows) ----------------
__global__ void __launch_bounds__(256)
ln1_window_kernel(const float* __restrict__ x,
                  const float* __restrict__ g,
                  const float* __restrict__ b,
                  float* __restrict__ y) {
    int wt = blockIdx.x;
    int wi = wt / NW, t = wt - wi * NW;
    int bb = wi / NWIN_B;
    int wrem = wi - bb * NWIN_B;
    int wr = wrem / NWIN_D, wc = wrem - wr * NWIN_D;
    int row = wr * WIN + t / WIN;
    int col = wc * WIN + (t % WIN);
    int tid = threadIdx.x;
    float* yr = y + (size_t)wt * DIM;
    if (row >= H0 || col >= W0) {
        yr[tid] = 0.f; yr[tid + 256] = 0.f; yr[tid + 512] = 0.f;
        return;
    }
    const float* xr = x + ((size_t)bb * NTOK + row * W0 + col) * DIM;
    float v0 = xr[tid], v1 = xr[tid + 256], v2 = xr[tid + 512];
    float mean = block_reduce_sum_256(v0 + v1 + v2) * (1.0f / DIM);
    float d0 = v0 - mean, d1 = v1 - mean, d2 = v2 - mean;
    float var = block_reduce_sum_256(d0 * d0 + d1 * d1 + d2 * d2) * (1.0f / DIM);
    float rs = rsqrtf(var + EPS);
    yr[tid]       = d0 * rs * g[tid]       + b[tid];
    yr[tid + 256] = d1 * rs * g[tid + 256] + b[tid + 256];
    yr[tid + 512] = d2 * rs * g[tid + 512] + b[tid + 512];
}

// ---------------- plain LN (rows of 768) ----------------
__global__ void __launch_bounds__(256)
ln_kernel(const float* __restrict__ in,
          const float* __restrict__ g,
          const float* __restrict__ b,
          float* __restrict__ out) {
    size_t row = blockIdx.x;
    int tid = threadIdx.x;
    const float* xr = in + row * DIM;
    float v0 = xr[tid], v1 = xr[tid + 256], v2 = xr[tid + 512];
    float mean = block_reduce_sum_256(v0 + v1 + v2) * (1.0f / DIM);
    float d0 = v0 - mean, d1 = v1 - mean, d2 = v2 - mean;
    float var = block_reduce_sum_256(d0 * d0 + d1 * d1 + d2 * d2) * (1.0f / DIM);
    float rs = rsqrtf(var + EPS);
    float* yr = out + row * DIM;
    yr[tid]       = d0 * rs * g[tid]       + b[tid];
    yr[tid + 256] = d1 * rs * g[tid + 256] + b[tid + 256];
    yr[tid + 512] = d2 * rs * g[tid + 512] + b[tid + 512];
}

// ---------------- tf32 helpers ----------------
__device__ __forceinline__ float to_tf32(float x) {
    float r;
    asm("cvt.rna.tf32.f32 %0, %1;" : "=f"(r) : "f"(x));
    return r;
}
__device__ __forceinline__ void mma_tf32(float* c, const float* a, const float* b) {
    uint32_t a0 = __float_as_uint(a[0]), a1 = __float_as_uint(a[1]);
    uint32_t a2 = __float_as_uint(a[2]), a3 = __float_as_uint(a[3]);
    uint32_t b0 = __float_as_uint(b[0]), b1 = __float_as_uint(b[1]);
    asm volatile(
        "mma.sync.aligned.m16n8k8.row.col.f32.tf32.tf32.f32 "
        "{%0,%1,%2,%3}, {%4,%5,%6,%7}, {%8,%9}, {%0,%1,%2,%3};"
        : "+f"(c[0]), "+f"(c[1]), "+f"(c[2]), "+f"(c[3])
        : "r"(a0), "r"(a1), "r"(a2), "r"(a3), "r"(b0), "r"(b1));
}

// ---------------- 128x128x16 tf32 GEMM, 4 warps (2x2 of 64x64) ----------------
// C[M,N] = A[M,K] * W[N,K]^T + bias. 128 threads.
// Square warp grid: sA and sB each read only 2x from smem (was 2x/4x with
// the 4x2 grid) -> 1.5x less LDS crossbar traffic per MMA.
// tf32 m16n8k8 fragment layout (validated R4/R10):
//   A: a0=(g,t4) a1=(g+8,t4) a2=(g,t4+4) a3=(g+8,t4+4)
//   B: b0=(k=t4,n=g) b1=(k=t4+4,n=g)
//   C: c0=(g,2t4) c1=(g,2t4+1) c2=(g+8,2t4) c3=(g+8,2t4+1)
//  EPI 0: store C
//  EPI 1: window-revert scatter: C[pos] = extra[pos] + val (pad tokens dropped)
//  EPI 2: store exact GELU(val)
//  EPI 3: store val + extra[m*N+n]
#define SPITCH 20
template <int EPI>
__global__ void __launch_bounds__(128, 2)
tgemm128(const float* __restrict__ A, const float* __restrict__ W,
         const float* __restrict__ bias, float* __restrict__ C,
         const float* __restrict__ extra, int M, int N, int K) {
    __shared__ float sA[2][128][SPITCH];
    __shared__ float sB[2][128][SPITCH];
    const int tid  = threadIdx.x;
    const int row0 = blockIdx.x * 128, col0 = blockIdx.y * 128;

    const int wid  = tid >> 5, lane = tid & 31;
    const int wm   = wid & 1, wn = wid >> 1;   // 2x2 grid, warp tile 64x64
    const int g    = lane >> 2, t4 = lane & 3;

    // gmem loaders: one row per thread, 16 k-floats per stage
    const bool aval = (row0 + tid) < M;
    const float* Ap = A + (size_t)(row0 + tid) * K;
    const float* Bp = W + (size_t)(col0 + tid) * K;

    float acc[4][8][4];
#pragma unroll
    for (int i = 0; i < 4; i++)
#pragma unroll
        for (int j = 0; j < 8; j++)
#pragma unroll
            for (int p = 0; p < 4; p++) acc[i][j][p] = 0.f;

    const int nt = K >> 4;
    float4 ra0, ra1, ra2, ra3, rb0, rb1, rb2, rb3;
    const float4 z4 = make_float4(0.f, 0.f, 0.f, 0.f);
    ra0 = aval ? *(const float4*)(Ap + 0)  : z4;
    ra1 = aval ? *(const float4*)(Ap + 4)  : z4;
    ra2 = aval ? *(const float4*)(Ap + 8)  : z4;
    ra3 = aval ? *(const float4*)(Ap + 12) : z4;
    rb0 = *(const float4*)(Bp + 0);
    rb1 = *(const float4*)(Bp + 4);
    rb2 = *(const float4*)(Bp + 8);
    rb3 = *(const float4*)(Bp + 12);
    {
        float* da = &sA[0][tid][0];
        float* db = &sB[0][tid][0];
        da[0] =to_tf32(ra0.x); da[1] =to_tf32(ra0.y); da[2] =to_tf32(ra0.z); da[3] =to_tf32(ra0.w);
        da[4] =to_tf32(ra1.x); da[5] =to_tf32(ra1.y); da[6] =to_tf32(ra1.z); da[7] =to_tf32(ra1.w);
        da[8] =to_tf32(ra2.x); da[9] =to_tf32(ra2.y); da[10]=to_tf32(ra2.z); da[11]=to_tf32(ra2.w);
        da[12]=to_tf32(ra3.x); da[13]=to_tf32(ra3.y); da[14]=to_tf32(ra3.z); da[15]=to_tf32(ra3.w);
        db[0] =to_tf32(rb0.x); db[1] =to_tf32(rb0.y); db[2] =to_tf32(rb0.z); db[3] =to_tf32(rb0.w);
        db[4] =to_tf32(rb1.x); db[5] =to_tf32(rb1.y); db[6] =to_tf32(rb1.z); db[7] =to_tf32(rb1.w);
        db[8] =to_tf32(rb2.x); db[9] =to_tf32(rb2.y); db[10]=to_tf32(rb2.z); db[11]=to_tf32(rb2.w);
        db[12]=to_tf32(rb3.x); db[13]=to_tf32(rb3.y); db[14]=to_tf32(rb3.z); db[15]=to_tf32(rb3.w);
    }
    __syncthreads();

    for (int kt = 0; kt < nt; kt++) {
        const int cur = kt & 1;
        if (kt + 1 < nt) {
            const float* ap = Ap + (size_t)(kt + 1) * 16;
            const float* bp = Bp + (size_t)(kt + 1) * 16;
            ra0 = aval ? *(const float4*)(ap + 0)  : z4;
            ra1 = aval ? *(const float4*)(ap + 4)  : z4;
            ra2 = aval ? *(const float4*)(ap + 8)  : z4;
            ra3 = aval ? *(const float4*)(ap + 12) : z4;
            rb0 = *(const float4*)(bp + 0);
            rb1 = *(const float4*)(bp + 4);
            rb2 = *(const float4*)(bp + 8);
            rb3 = *(const float4*)(bp + 12);
        }
#pragma unroll
        for (int ks = 0; ks < 2; ks++) {
            const int k0 = ks * 8;
            float af[4][4];
#pragma unroll
            for (int i = 0; i < 4; i++) {
                const int mrow = wm * 64 + i * 16 + g;
                af[i][0] = sA[cur][mrow    ][k0 + t4];
                af[i][1] = sA[cur][mrow + 8][k0 + t4];
                af[i][2] = sA[cur][mrow    ][k0 + t4 + 4];
                af[i][3] = sA[cur][mrow + 8][k0 + t4 + 4];
            }
#pragma unroll
            for (int j = 0; j < 8; j++) {
                const int nrow = wn * 64 + j * 8 + g;
                float bf[2];
                bf[0] = sB[cur][nrow][k0 + t4];
                bf[1] = sB[cur][nrow][k0 + t4 + 4];
#pragma unroll
                for (int i = 0; i < 4; i++)
                    mma_tf32(acc[i][j], af[i], bf);
            }
        }
        if (kt + 1 < nt) {
            const int nxt = cur ^ 1;
            float* da = &sA[nxt][tid][0];
            float* db = &sB[nxt][tid][0];
            da[0] =to_tf32(ra0.x); da[1] =to_tf32(ra0.y); da[2] =to_tf32(ra0.z); da[3] =to_tf32(ra0.w);
            da[4] =to_tf32(ra1.x); da[5] =to_tf32(ra1.y); da[6] =to_tf32(ra1.z); da[7] =to_tf32(ra1.w);
            da[8] =to_tf32(ra2.x); da[9] =to_tf32(ra2.y); da[10]=to_tf32(ra2.z); da[11]=to_tf32(ra2.w);
            da[12]=to_tf32(ra3.x); da[13]=to_tf32(ra3.y); da[14]=to_tf32(ra3.z); da[15]=to_tf32(ra3.w);
            db[0] =to_tf32(rb0.x); db[1] =to_tf32(rb0.y); db[2] =to_tf32(rb0.z); db[3] =to_tf32(rb0.w);
            db[4] =to_tf32(rb1.x); db[5] =to_tf32(rb1.y); db[6] =to_tf32(rb1.z); db[7] =to_tf32(rb1.w);
            db[8] =to_tf32(rb2.x); db[9] =to_tf32(rb2.y); db[10]=to_tf32(rb2.z); db[11]=to_tf32(rb2.w);
            db[12]=to_tf32(rb3.x); db[13]=to_tf32(rb3.y); db[14]=to_tf32(rb3.z); db[15]=to_tf32(rb3.w);
            __syncthreads();
        }
    }

    // ---------------- epilogue ----------------
    // thread owns rows {wm*64 + i*16 + r*8 + g}, cols col0 + {wn*64 + j*8 + 2*t4 + p}
    float bcol[8][2];
#pragma unroll
    for (int j = 0; j < 8; j++) {
        int c = col0 + wn * 64 + j * 8 + 2 * t4;
        bcol[j][0] = bias[c];
        bcol[j][1] = bias[c + 1];
    }
#pragma unroll
    for (int i = 0; i < 4; i++) {
#pragma unroll
        for (int r = 0; r < 2; r++) {
            int m = row0 + wm * 64 + i * 16 + r * 8 + g;
            if (m >= M) continue;
            if (EPI == 1) {
                int wi = m / NW, t = m - wi * NW;
                int bb = wi / NWIN_B;
                int wrem = wi - bb * NWIN_B;
                int wr = wrem / NWIN_D, wc = wrem - wr * NWIN_D;
                int rr = wr * WIN + t / WIN;
                int cc = wc * WIN + (t % WIN);
                if (rr < H0 && cc < W0) {
                    size_t ob = ((size_t)bb * NTOK + rr * W0 + cc) * DIM;
#pragma unroll
                    for (int j = 0; j < 8; j++) {
                        size_t o = ob + col0 + wn * 64 + j * 8 + 2 * t4;
                        float v0 = acc[i][j][r * 2]     + bcol[j][0] + extra[o];
                        float v1 = acc[i][j][r * 2 + 1] + bcol[j][1] + extra[o + 1];
                        *(float2*)&C[o] = make_float2(v0, v1);
                    }
                }
            } else {
                size_t ob = (size_t)m * N + col0 + wn * 64;
#pragma unroll
                for (int j = 0; j < 8; j++) {
                    size_t o = ob + j * 8 + 2 * t4;
                    float v0 = acc[i][j][r * 2]     + bcol[j][0];
                    float v1 = acc[i][j][r * 2 + 1] + bcol[j][1];
                    if (EPI == 2) {
                        v0 = 0.5f * v0 * (1.0f + erff(v0 * 0.70710678118654752f));
                        v1 = 0.5f * v1 * (1.0f + erff(v1 * 0.70710678118654752f));
                    } else if (EPI == 3) {
                        v0 += extra[o];
                        v1 += extra[o + 1];
                    }
                    *(float2*)&C[o] = make_float2(v0, v1);
                }
            }
        }
    }
}

// ---------------- windowed attention, one (window, head) per block ----------------
__global__ void __launch_bounds__(224)
attn_kernel(const float* __restrict__ qkv,
            const float* __restrict__ rel,
            float* __restrict__ outp) {
    extern __shared__ float sm[];
    float* sk = sm;
    float* sv = sm + NW * DH;
    int wi = blockIdx.x / HEADS;
    int h  = blockIdx.x - wi * HEADS;
    int tid = threadIdx.x;
    size_t base = (size_t)wi * NW * QKV_N + h * DH;
    for (int idx = tid; idx < NW * DH; idx += 224) {
        int t = idx >> 6, d = idx & 63;
        size_t o = base + (size_t)t * QKV_N + d;
        sk[idx] = qkv[o + DIM];
        sv[idx] = qkv[o + 2 * DIM];
    }
    __syncthreads();
    if (tid >= NW) return;

    float q[DH];
    {
        const float4* qp = (const float4*)(qkv + base + (size_t)tid * QKV_N);
#pragma unroll
        for (int i = 0; i < 16; i++) {
            float4 qq = qp[i];
            q[4 * i]     = qq.x * SCALE;
            q[4 * i + 1] = qq.y * SCALE;
            q[4 * i + 2] = qq.z * SCALE;
            q[4 * i + 3] = qq.w * SCALE;
        }
    }
    float acc[DH];
#pragma unroll
    for (int i = 0; i < DH; i++) acc[i] = 0.f;
    float mx = -1e30f, l = 0.f;
    const float* brow = rel + ((size_t)h * NW + tid) * NW;

    for (int j = 0; j < NW; j++) {
        const float4* kp = (const float4*)(sk + j * DH);
        float s = 0.f;
#pragma unroll
        for (int i = 0; i < 16; i++) {
            float4 kk = kp[i];
            s += q[4 * i] * kk.x + q[4 * i + 1] * kk.y
               + q[4 * i + 2] * kk.z + q[4 * i + 3] * kk.w;
        }
        s += brow[j];
        const float4* vp = (const float4*)(sv + j * DH);
        if (s <= mx) {
            float p = __expf(s - mx);
            l += p;
#pragma unroll
            for (int i = 0; i < 16; i++) {
                float4 vv = vp[i];
                acc[4 * i]     += p * vv.x;
                acc[4 * i + 1] += p * vv.y;
                acc[4 * i + 2] += p * vv.z;
                acc[4 * i + 3] += p * vv.w;
            }
        } else {
            float c = __expf(mx - s);
            l = l * c + 1.f;
            mx = s;
#pragma unroll
            for (int i = 0; i < 16; i++) {
                float4 vv = vp[i];
                acc[4 * i]     = acc[4 * i]     * c + vv.x;
                acc[4 * i + 1] = acc[4 * i + 1] * c + vv.y;
                acc[4 * i + 2] = acc[4 * i + 2] * c + vv.z;
                acc[4 * i + 3] = acc[4 * i + 3] * c + vv.w;
            }
        }
    }
    float inv = 1.0f / l;
    float4* op = (float4*)(outp + (size_t)(wi * NW + tid) * DIM + h * DH);
#pragma unroll
    for (int i = 0; i < 16; i++) {
        op[i] = make_float4(acc[4 * i] * inv, acc[4 * i + 1] * inv,
                            acc[4 * i + 2] * inv, acc[4 * i + 3] * inv);
    }
}

// ---------------- launcher ----------------
extern "C" void kernel_launch(void* const* d_in, const int* in_sizes, int n_in,
                              void* d_out, int out_size) {
    const float* x      = (const float*)d_in[0];
    const float* rel    = (const float*)d_in[1];
    const float* ln1_g  = (const float*)d_in[2];
    const float* ln1_b  = (const float*)d_in[3];
    const float* qkv_w  = (const float*)d_in[4];
    const float* qkv_b  = (const float*)d_in[5];
    const float* proj_w = (const float*)d_in[6];
    const float* proj_b = (const float*)d_in[7];
    const float* ln2_g  = (const float*)d_in[8];
    const float* ln2_b  = (const float*)d_in[9];
    const float* fc1_w  = (const float*)d_in[10];
    const float* fc1_b  = (const float*)d_in[11];
    const float* fc2_w  = (const float*)d_in[12];
    const float* fc2_b  = (const float*)d_in[13];
    float* out = (float*)d_out;

    float *p_xw, *p_qkv, *p_attnout, *p_x1, *p_ln2, *p_mlp;
    cudaGetSymbolAddress((void**)&p_xw,      g_xw);
    cudaGetSymbolAddress((void**)&p_qkv,     g_qkv);
    cudaGetSymbolAddress((void**)&p_attnout, g_attnout);
    cudaGetSymbolAddress((void**)&p_x1,      g_x1);
    cudaGetSymbolAddress((void**)&p_ln2,     g_ln2);
    cudaGetSymbolAddress((void**)&p_mlp,     g_mlp);

    const int attn_smem = 2 * NW * DH * (int)sizeof(float);  // 100352 B
    cudaFuncSetAttribute(attn_kernel, cudaFuncAttributeMaxDynamicSharedMemorySize, attn_smem);

    // 1. LN1 + window partition
    ln1_window_kernel<<<MWIN, 256>>>(x, ln1_g, ln1_b, p_xw);

    // 2. QKV
    tgemm128<0><<<dim3((MWIN + 127) / 128, QKV_N / 128), 128>>>(
        p_xw, qkv_w, qkv_b, p_qkv, nullptr, MWIN, QKV_N, DIM);

    // 3. Windowed attention
    attn_kernel<<<NWINTOT * HEADS, 224, attn_smem>>>(p_qkv, rel, p_attnout);

    // 4. Projection + window revert + residual
    tgemm128<1><<<dim3((MWIN + 127) / 128, DIM / 128), 128>>>(
        p_attnout, proj_w, proj_b, p_x1, x, MWIN, DIM, DIM);

    // 5. LN2
    ln_kernel<<<MTOK, 256>>>(p_x1, ln2_g, ln2_b, p_ln2);

    // 6. fc1 + exact GELU
    tgemm128<2><<<dim3(MTOK / 128, MLP_H / 128), 128>>>(
        p_ln2, fc1_w, fc1_b, p_mlp, nullptr, MTOK, MLP_H, DIM);

    // 7. fc2 + residual -> d_out
    tgemm128<3><<<dim3(MTOK / 128, DIM / 128), 128>>>(
        p_mlp, fc2_w, fc2_b, out, p_x1, MTOK, DIM, MLP_H);
}

// round 13
// speedup vs baseline: 1.4565x; 1.4565x over previous
#include <cuda_runtime.h>
#include <math.h>
#include <stdint.h>

// ---------------- problem constants ----------------
#define DIM     768
#define HEADS   12
#define DH      64
#define WIN     14
#define NW      196          // WIN*WIN
#define BATCH   8
#define H0      64
#define W0      64
#define NTOK    4096         // H0*W0
#define NWIN_D  5            // windows per spatial dim (70/14)
#define NWIN_B  25           // windows per batch image
#define NWINTOT 200          // BATCH * NWIN_B
#define MWIN    (NWINTOT*NW) // 39200 windowed tokens
#define MTOK    (BATCH*NTOK) // 32768 real tokens
#define MLP_H   3072
#define QKV_N   (3*DIM)      // 2304
#define SCALE   0.125f
#define EPS     1e-5f

// ---------------- scratch (static device globals; no allocations) ----------------
__device__ float g_xw[(size_t)MWIN * DIM];
__device__ float g_qkv[(size_t)MWIN * QKV_N];
__device__ float g_attnout[(size_t)MWIN * DIM];
__device__ float g_x1[(size_t)MTOK * DIM];
__device__ float g_ln2[(size_t)MTOK * DIM];
__device__ float g_mlp[(size_t)MTOK * MLP_H];

// ---------------- block reduction ----------------
__device__ __forceinline__ float block_reduce_sum_256(float v) {
    __shared__ float red[8];
    int lane = threadIdx.x & 31, wid = threadIdx.x >> 5;
#pragma unroll
    for (int o = 16; o; o >>= 1) v += __shfl_xor_sync(0xffffffffu, v, o);
    __syncthreads();
    if (lane == 0) red[wid] = v;
    __syncthreads();
    float s = red[0];
#pragma unroll
    for (int i = 1; i < 8; i++) s += red[i];
    return s;
}

// ---------------- LN1 + window partition (pads -> zero rows) ----------------
__global__ void __launch_bounds__(256)
ln1_window_kernel(const float* __restrict__ x,
                  const float* __restrict__ g,
                  const float* __restrict__ b,
                  float* __restrict__ y) {
    int wt = blockIdx.x;
    int wi = wt / NW, t = wt - wi * NW;
    int bb = wi / NWIN_B;
    int wrem = wi - bb * NWIN_B;
    int wr = wrem / NWIN_D, wc = wrem - wr * NWIN_D;
    int row = wr * WIN + t / WIN;
    int col = wc * WIN + (t % WIN);
    int tid = threadIdx.x;
    float* yr = y + (size_t)wt * DIM;
    if (row >= H0 || col >= W0) {
        yr[tid] = 0.f; yr[tid + 256] = 0.f; yr[tid + 512] = 0.f;
        return;
    }
    const float* xr = x + ((size_t)bb * NTOK + row * W0 + col) * DIM;
    float v0 = xr[tid], v1 = xr[tid + 256], v2 = xr[tid + 512];
    float mean = block_reduce_sum_256(v0 + v1 + v2) * (1.0f / DIM);
    float d0 = v0 - mean, d1 = v1 - mean, d2 = v2 - mean;
    float var = block_reduce_sum_256(d0 * d0 + d1 * d1 + d2 * d2) * (1.0f / DIM);
    float rs = rsqrtf(var + EPS);
    yr[tid]       = d0 * rs * g[tid]       + b[tid];
    yr[tid + 256] = d1 * rs * g[tid + 256] + b[tid + 256];
    yr[tid + 512] = d2 * rs * g[tid + 512] + b[tid + 512];
}

// ---------------- plain LN (rows of 768) ----------------
__global__ void __launch_bounds__(256)
ln_kernel(const float* __restrict__ in,
          const float* __restrict__ g,
          const float* __restrict__ b,
          float* __restrict__ out) {
    size_t row = blockIdx.x;
    int tid = threadIdx.x;
    const float* xr = in + row * DIM;
    float v0 = xr[tid], v1 = xr[tid + 256], v2 = xr[tid + 512];
    float mean = block_reduce_sum_256(v0 + v1 + v2) * (1.0f / DIM);
    float d0 = v0 - mean, d1 = v1 - mean, d2 = v2 - mean;
    float var = block_reduce_sum_256(d0 * d0 + d1 * d1 + d2 * d2) * (1.0f / DIM);
    float rs = rsqrtf(var + EPS);
    float* yr = out + row * DIM;
    yr[tid]       = d0 * rs * g[tid]       + b[tid];
    yr[tid + 256] = d1 * rs * g[tid + 256] + b[tid + 256];
    yr[tid + 512] = d2 * rs * g[tid + 512] + b[tid + 512];
}

// ---------------- tf32 helpers ----------------
__device__ __forceinline__ float to_tf32(float x) {
    float r;
    asm("cvt.rna.tf32.f32 %0, %1;" : "=f"(r) : "f"(x));
    return r;
}
__device__ __forceinline__ void mma_tf32(float* c, const float* a, const float* b) {
    uint32_t a0 = __float_as_uint(a[0]), a1 = __float_as_uint(a[1]);
    uint32_t a2 = __float_as_uint(a[2]), a3 = __float_as_uint(a[3]);
    uint32_t b0 = __float_as_uint(b[0]), b1 = __float_as_uint(b[1]);
    asm volatile(
        "mma.sync.aligned.m16n8k8.row.col.f32.tf32.tf32.f32 "
        "{%0,%1,%2,%3}, {%4,%5,%6,%7}, {%8,%9}, {%0,%1,%2,%3};"
        : "+f"(c[0]), "+f"(c[1]), "+f"(c[2]), "+f"(c[3])
        : "r"(a0), "r"(a1), "r"(a2), "r"(a3), "r"(b0), "r"(b1));
}

// ---------------- cp.async helpers ----------------
__device__ __forceinline__ void cp_async16(uint32_t dst_smem, const void* src, int src_bytes) {
    asm volatile("cp.async.cg.shared.global [%0], [%1], 16, %2;\n"
                 :: "r"(dst_smem), "l"(src), "r"(src_bytes));
}
__device__ __forceinline__ void cp_commit() {
    asm volatile("cp.async.commit_group;\n" ::: "memory");
}
template <int N>
__device__ __forceinline__ void cp_wait() {
    asm volatile("cp.async.wait_group %0;\n" :: "n"(N) : "memory");
}

// ---------------- 128x128x16 tf32 GEMM, cp.async 4-stage pipeline ----------------
// C[M,N] = A[M,K] * W[N,K]^T + bias. 256 threads = 8 warps (4x2), warp 32x64.
// (R10 config — best measured — plus LDGSTS: no reg staging, no STS, 4-stage.)
// tf32 m16n8k8 fragment layout (validated R4/R10):
//   A: a0=(g,t4) a1=(g+8,t4) a2=(g,t4+4) a3=(g+8,t4+4)
//   B: b0=(k=t4,n=g) b1=(k=t4+4,n=g)
//   C: c0=(g,2t4) c1=(g,2t4+1) c2=(g+8,2t4) c3=(g+8,2t4+1)
// cvt.rna.tf32 applied on fragments after LDS (same math as R10).
//  EPI 0: store C
//  EPI 1: window-revert scatter: C[pos] = extra[pos] + val (pad tokens dropped)
//  EPI 2: store exact GELU(val)
//  EPI 3: store val + extra[m*N+n]
#define SPITCH 20
#define STAGEF (128 * SPITCH)          // floats per stage per matrix
#define GSMEM  (2 * 4 * STAGEF * 4)    // dyn smem bytes: 2 matrices x 4 stages

template <int EPI>
__global__ void __launch_bounds__(256, 2)
tgemm128(const float* __restrict__ A, const float* __restrict__ W,
         const float* __restrict__ bias, float* __restrict__ C,
         const float* __restrict__ extra, int M, int N, int K) {
    extern __shared__ float sm[];
    float* sA = sm;                    // [4][128][SPITCH]
    float* sB = sm + 4 * STAGEF;
    const uint32_t sA_u = (uint32_t)__cvta_generic_to_shared(sA);
    const uint32_t sB_u = (uint32_t)__cvta_generic_to_shared(sB);

    const int tid  = threadIdx.x;
    const int row0 = blockIdx.x * 128, col0 = blockIdx.y * 128;

    const int wid  = tid >> 5, lane = tid & 31;
    const int wm   = wid & 3, wn = wid >> 2;   // warp tile: rows wm*32, cols wn*64
    const int g    = lane >> 2, t4 = lane & 3;

    // loader mapping: quads q = tid and tid+256 over 512 quads per matrix-stage
    // quad q -> row q>>2, k-quad (q&3)*4
    const int r0q = tid >> 2,  k0q = (tid & 3) * 4;
    const int r1q = r0q + 64;  // second quad: (tid+256)>>2 = r0q+64, same k-quad
    const int a0row = row0 + r0q, a1row = row0 + r1q;
    const int a0b = (a0row < M) ? 16 : 0;
    const int a1b = (a1row < M) ? 16 : 0;
    const float* A0 = A + (size_t)(a0row < M ? a0row : M - 1) * K + k0q;
    const float* A1 = A + (size_t)(a1row < M ? a1row : M - 1) * K + k0q;
    const float* B0 = W + (size_t)(col0 + r0q) * K + k0q;
    const float* B1 = W + (size_t)(col0 + r1q) * K + k0q;
    const uint32_t dA0 = sA_u + (uint32_t)(r0q * SPITCH + k0q) * 4;
    const uint32_t dA1 = sA_u + (uint32_t)(r1q * SPITCH + k0q) * 4;
    const uint32_t dB0 = sB_u + (uint32_t)(r0q * SPITCH + k0q) * 4;
    const uint32_t dB1 = sB_u + (uint32_t)(r1q * SPITCH + k0q) * 4;
    const uint32_t stb = STAGEF * 4;   // stage stride in bytes

    float acc[2][8][4];
#pragma unroll
    for (int i = 0; i < 2; i++)
#pragma unroll
        for (int j = 0; j < 8; j++)
#pragma unroll
            for (int p = 0; p < 4; p++) acc[i][j][p] = 0.f;

    const int nt = K >> 4;

    // prologue: stages 0..2
#pragma unroll
    for (int s = 0; s < 3; s++) {
        const size_t ko = (size_t)s * 16;
        cp_async16(dA0 + s * stb, A0 + ko, a0b);
        cp_async16(dA1 + s * stb, A1 + ko, a1b);
        cp_async16(dB0 + s * stb, B0 + ko, 16);
        cp_async16(dB1 + s * stb, B1 + ko, 16);
        cp_commit();
    }

    for (int kt = 0; kt < nt; kt++) {
        cp_wait<2>();          // stage kt complete
        __syncthreads();
        const int st = (kt & 3) * STAGEF;
#pragma unroll
        for (int ks = 0; ks < 2; ks++) {
            const int k0 = ks * 8;
            float af[2][4], bf[8][2];
#pragma unroll
            for (int i = 0; i < 2; i++) {
                const int mrow = wm * 32 + i * 16 + g;
                af[i][0] = to_tf32(sA[st + mrow * SPITCH       + k0 + t4]);
                af[i][1] = to_tf32(sA[st + (mrow + 8) * SPITCH + k0 + t4]);
                af[i][2] = to_tf32(sA[st + mrow * SPITCH       + k0 + t4 + 4]);
                af[i][3] = to_tf32(sA[st + (mrow + 8) * SPITCH + k0 + t4 + 4]);
            }
#pragma unroll
            for (int j = 0; j < 8; j++) {
                const int nrow = wn * 64 + j * 8 + g;
                bf[j][0] = to_tf32(sB[st + nrow * SPITCH + k0 + t4]);
                bf[j][1] = to_tf32(sB[st + nrow * SPITCH + k0 + t4 + 4]);
            }
#pragma unroll
            for (int i = 0; i < 2; i++)
#pragma unroll
                for (int j = 0; j < 8; j++)
                    mma_tf32(acc[i][j], af[i], bf[j]);
        }
        // issue stage kt+3 into buffer (kt+3)%4 (consumed at kt-1; safe after barrier)
        if (kt + 3 < nt) {
            const int s = (kt + 3) & 3;
            const size_t ko = (size_t)(kt + 3) * 16;
            cp_async16(dA0 + s * stb, A0 + ko, a0b);
            cp_async16(dA1 + s * stb, A1 + ko, a1b);
            cp_async16(dB0 + s * stb, B0 + ko, 16);
            cp_async16(dB1 + s * stb, B1 + ko, 16);
        }
        cp_commit();
    }

    // ---------------- epilogue ----------------
    float bcol[8][2];
#pragma unroll
    for (int j = 0; j < 8; j++) {
        int c = col0 + wn * 64 + j * 8 + 2 * t4;
        bcol[j][0] = bias[c];
        bcol[j][1] = bias[c + 1];
    }
#pragma unroll
    for (int i = 0; i < 2; i++) {
#pragma unroll
        for (int r = 0; r < 2; r++) {
            int m = row0 + wm * 32 + i * 16 + r * 8 + g;
            if (m >= M) continue;
            if (EPI == 1) {
                int wi = m / NW, t = m - wi * NW;
                int bb = wi / NWIN_B;
                int wrem = wi - bb * NWIN_B;
                int wr = wrem / NWIN_D, wc = wrem - wr * NWIN_D;
                int rr = wr * WIN + t / WIN;
                int cc = wc * WIN + (t % WIN);
                if (rr < H0 && cc < W0) {
                    size_t ob = ((size_t)bb * NTOK + rr * W0 + cc) * DIM;
#pragma unroll
                    for (int j = 0; j < 8; j++) {
                        size_t o = ob + col0 + wn * 64 + j * 8 + 2 * t4;
                        float v0 = acc[i][j][r * 2]     + bcol[j][0] + extra[o];
                        float v1 = acc[i][j][r * 2 + 1] + bcol[j][1] + extra[o + 1];
                        *(float2*)&C[o] = make_float2(v0, v1);
                    }
                }
            } else {
                size_t ob = (size_t)m * N + col0 + wn * 64;
#pragma unroll
                for (int j = 0; j < 8; j++) {
                    size_t o = ob + j * 8 + 2 * t4;
                    float v0 = acc[i][j][r * 2]     + bcol[j][0];
                    float v1 = acc[i][j][r * 2 + 1] + bcol[j][1];
                    if (EPI == 2) {
                        v0 = 0.5f * v0 * (1.0f + erff(v0 * 0.70710678118654752f));
                        v1 = 0.5f * v1 * (1.0f + erff(v1 * 0.70710678118654752f));
                    } else if (EPI == 3) {
                        v0 += extra[o];
                        v1 += extra[o + 1];
                    }
                    *(float2*)&C[o] = make_float2(v0, v1);
                }
            }
        }
    }
}

// ---------------- windowed attention, one (window, head) per block ----------------
__global__ void __launch_bounds__(224)
attn_kernel(const float* __restrict__ qkv,
            const float* __restrict__ rel,
            float* __restrict__ outp) {
    extern __shared__ float smx[];
    float* sk = smx;
    float* sv = smx + NW * DH;
    int wi = blockIdx.x / HEADS;
    int h  = blockIdx.x - wi * HEADS;
    int tid = threadIdx.x;
    size_t base = (size_t)wi * NW * QKV_N + h * DH;
    for (int idx = tid; idx < NW * DH; idx += 224) {
        int t = idx >> 6, d = idx & 63;
        size_t o = base + (size_t)t * QKV_N + d;
        sk[idx] = qkv[o + DIM];
        sv[idx] = qkv[o + 2 * DIM];
    }
    __syncthreads();
    if (tid >= NW) return;

    float q[DH];
    {
        const float4* qp = (const float4*)(qkv + base + (size_t)tid * QKV_N);
#pragma unroll
        for (int i = 0; i < 16; i++) {
            float4 qq = qp[i];
            q[4 * i]     = qq.x * SCALE;
            q[4 * i + 1] = qq.y * SCALE;
            q[4 * i + 2] = qq.z * SCALE;
            q[4 * i + 3] = qq.w * SCALE;
        }
    }
    float acc[DH];
#pragma unroll
    for (int i = 0; i < DH; i++) acc[i] = 0.f;
    float mx = -1e30f, l = 0.f;
    const float* brow = rel + ((size_t)h * NW + tid) * NW;

    for (int j = 0; j < NW; j++) {
        const float4* kp = (const float4*)(sk + j * DH);
        float s = 0.f;
#pragma unroll
        for (int i = 0; i < 16; i++) {
            float4 kk = kp[i];
            s += q[4 * i] * kk.x + q[4 * i + 1] * kk.y
               + q[4 * i + 2] * kk.z + q[4 * i + 3] * kk.w;
        }
        s += brow[j];
        const float4* vp = (const float4*)(sv + j * DH);
        if (s <= mx) {
            float p = __expf(s - mx);
            l += p;
#pragma unroll
            for (int i = 0; i < 16; i++) {
                float4 vv = vp[i];
                acc[4 * i]     += p * vv.x;
                acc[4 * i + 1] += p * vv.y;
                acc[4 * i + 2] += p * vv.z;
                acc[4 * i + 3] += p * vv.w;
            }
        } else {
            float c = __expf(mx - s);
            l = l * c + 1.f;
            mx = s;
#pragma unroll
            for (int i = 0; i < 16; i++) {
                float4 vv = vp[i];
                acc[4 * i]     = acc[4 * i]     * c + vv.x;
                acc[4 * i + 1] = acc[4 * i + 1] * c + vv.y;
                acc[4 * i + 2] = acc[4 * i + 2] * c + vv.z;
                acc[4 * i + 3] = acc[4 * i + 3] * c + vv.w;
            }
        }
    }
    float inv = 1.0f / l;
    float4* op = (float4*)(outp + (size_t)(wi * NW + tid) * DIM + h * DH);
#pragma unroll
    for (int i = 0; i < 16; i++) {
        op[i] = make_float4(acc[4 * i] * inv, acc[4 * i + 1] * inv,
                            acc[4 * i + 2] * inv, acc[4 * i + 3] * inv);
    }
}

// ---------------- launcher ----------------
extern "C" void kernel_launch(void* const* d_in, const int* in_sizes, int n_in,
                              void* d_out, int out_size) {
    const float* x      = (const float*)d_in[0];
    const float* rel    = (const float*)d_in[1];
    const float* ln1_g  = (const float*)d_in[2];
    const float* ln1_b  = (const float*)d_in[3];
    const float* qkv_w  = (const float*)d_in[4];
    const float* qkv_b  = (const float*)d_in[5];
    const float* proj_w = (const float*)d_in[6];
    const float* proj_b = (const float*)d_in[7];
    const float* ln2_g  = (const float*)d_in[8];
    const float* ln2_b  = (const float*)d_in[9];
    const float* fc1_w  = (const float*)d_in[10];
    const float* fc1_b  = (const float*)d_in[11];
    const float* fc2_w  = (const float*)d_in[12];
    const float* fc2_b  = (const float*)d_in[13];
    float* out = (float*)d_out;

    float *p_xw, *p_qkv, *p_attnout, *p_x1, *p_ln2, *p_mlp;
    cudaGetSymbolAddress((void**)&p_xw,      g_xw);
    cudaGetSymbolAddress((void**)&p_qkv,     g_qkv);
    cudaGetSymbolAddress((void**)&p_attnout, g_attnout);
    cudaGetSymbolAddress((void**)&p_x1,      g_x1);
    cudaGetSymbolAddress((void**)&p_ln2,     g_ln2);
    cudaGetSymbolAddress((void**)&p_mlp,     g_mlp);

    const int attn_smem = 2 * NW * DH * (int)sizeof(float);  // 100352 B
    cudaFuncSetAttribute(attn_kernel, cudaFuncAttributeMaxDynamicSharedMemorySize, attn_smem);
    cudaFuncSetAttribute(tgemm128<0>, cudaFuncAttributeMaxDynamicSharedMemorySize, GSMEM);
    cudaFuncSetAttribute(tgemm128<1>, cudaFuncAttributeMaxDynamicSharedMemorySize, GSMEM);
    cudaFuncSetAttribute(tgemm128<2>, cudaFuncAttributeMaxDynamicSharedMemorySize, GSMEM);
    cudaFuncSetAttribute(tgemm128<3>, cudaFuncAttributeMaxDynamicSharedMemorySize, GSMEM);

    // 1. LN1 + window partition
    ln1_window_kernel<<<MWIN, 256>>>(x, ln1_g, ln1_b, p_xw);

    // 2. QKV
    tgemm128<0><<<dim3((MWIN + 127) / 128, QKV_N / 128), 256, GSMEM>>>(
        p_xw, qkv_w, qkv_b, p_qkv, nullptr, MWIN, QKV_N, DIM);

    // 3. Windowed attention
    attn_kernel<<<NWINTOT * HEADS, 224, attn_smem>>>(p_qkv, rel, p_attnout);

    // 4. Projection + window revert + residual
    tgemm128<1><<<dim3((MWIN + 127) / 128, DIM / 128), 256, GSMEM>>>(
        p_attnout, proj_w, proj_b, p_x1, x, MWIN, DIM, DIM);

    // 5. LN2
    ln_kernel<<<MTOK, 256>>>(p_x1, ln2_g, ln2_b, p_ln2);

    // 6. fc1 + exact GELU
    tgemm128<2><<<dim3(MTOK / 128, MLP_H / 128), 256, GSMEM>>>(
        p_ln2, fc1_w, fc1_b, p_mlp, nullptr, MTOK, MLP_H, DIM);

    // 7. fc2 + residual -> d_out
    tgemm128<3><<<dim3(MTOK / 128, DIM / 128), 256, GSMEM>>>(
        p_mlp, fc2_w, fc2_b, out, p_x1, MTOK, DIM, MLP_H);
}

// round 14
// speedup vs baseline: 1.6391x; 1.1253x over previous
#include <cuda_runtime.h>
#include <math.h>
#include <stdint.h>

// ---------------- problem constants ----------------
#define DIM     768
#define HEADS   12
#define DH      64
#define WIN     14
#define NW      196          // WIN*WIN
#define BATCH   8
#define H0      64
#define W0      64
#define NTOK    4096         // H0*W0
#define NWIN_D  5            // windows per spatial dim (70/14)
#define NWIN_B  25           // windows per batch image
#define NWINTOT 200          // BATCH * NWIN_B
#define MWIN    (NWINTOT*NW) // 39200 windowed tokens
#define MTOK    (BATCH*NTOK) // 32768 real tokens
#define MLP_H   3072
#define QKV_N   (3*DIM)      // 2304
#define SCALE   0.125f
#define EPS     1e-5f

// ---------------- scratch (static device globals; no allocations) ----------------
__device__ float g_xw[(size_t)MWIN * DIM];
__device__ float g_qkv[(size_t)MWIN * QKV_N];
__device__ float g_attnout[(size_t)MWIN * DIM];
__device__ float g_x1[(size_t)MTOK * DIM];
__device__ float g_ln2[(size_t)MTOK * DIM];
__device__ float g_mlp[(size_t)MTOK * MLP_H];
// tf32-rounded weight copies
__device__ float g_wq[(size_t)QKV_N * DIM];
__device__ float g_wp[(size_t)DIM * DIM];
__device__ float g_w1[(size_t)MLP_H * DIM];
__device__ float g_w2[(size_t)DIM * MLP_H];

// ---------------- tf32 helpers ----------------
__device__ __forceinline__ float to_tf32(float x) {
    float r;
    asm("cvt.rna.tf32.f32 %0, %1;" : "=f"(r) : "f"(x));
    return r;
}
__device__ __forceinline__ void mma_tf32(float* c, const float* a, const float* b) {
    uint32_t a0 = __float_as_uint(a[0]), a1 = __float_as_uint(a[1]);
    uint32_t a2 = __float_as_uint(a[2]), a3 = __float_as_uint(a[3]);
    uint32_t b0 = __float_as_uint(b[0]), b1 = __float_as_uint(b[1]);
    asm volatile(
        "mma.sync.aligned.m16n8k8.row.col.f32.tf32.tf32.f32 "
        "{%0,%1,%2,%3}, {%4,%5,%6,%7}, {%8,%9}, {%0,%1,%2,%3};"
        : "+f"(c[0]), "+f"(c[1]), "+f"(c[2]), "+f"(c[3])
        : "r"(a0), "r"(a1), "r"(a2), "r"(a3), "r"(b0), "r"(b1));
}

// ---------------- weight tf32 pre-round (one-shot, idempotent) ----------------
__global__ void __launch_bounds__(256)
cvt_tf32_kernel(const float* __restrict__ in, float* __restrict__ out, int n) {
    int i = (blockIdx.x * 256 + threadIdx.x) * 4;
    if (i < n) {
        float4 v = *(const float4*)(in + i);
        v.x = to_tf32(v.x); v.y = to_tf32(v.y);
        v.z = to_tf32(v.z); v.w = to_tf32(v.w);
        *(float4*)(out + i) = v;
    }
}

// ---------------- block reduction ----------------
__device__ __forceinline__ float block_reduce_sum_256(float v) {
    __shared__ float red[8];
    int lane = threadIdx.x & 31, wid = threadIdx.x >> 5;
#pragma unroll
    for (int o = 16; o; o >>= 1) v += __shfl_xor_sync(0xffffffffu, v, o);
    __syncthreads();
    if (lane == 0) red[wid] = v;
    __syncthreads();
    float s = red[0];
#pragma unroll
    for (int i = 1; i < 8; i++) s += red[i];
    return s;
}

// ---------------- LN1 + window partition (pads -> zero rows; tf32-rounded out) ----------------
__global__ void __launch_bounds__(256)
ln1_window_kernel(const float* __restrict__ x,
                  const float* __restrict__ g,
                  const float* __restrict__ b,
                  float* __restrict__ y) {
    int wt = blockIdx.x;
    int wi = wt / NW, t = wt - wi * NW;
    int bb = wi / NWIN_B;
    int wrem = wi - bb * NWIN_B;
    int wr = wrem / NWIN_D, wc = wrem - wr * NWIN_D;
    int row = wr * WIN + t / WIN;
    int col = wc * WIN + (t % WIN);
    int tid = threadIdx.x;
    float* yr = y + (size_t)wt * DIM;
    if (row >= H0 || col >= W0) {
        yr[tid] = 0.f; yr[tid + 256] = 0.f; yr[tid + 512] = 0.f;
        return;
    }
    const float* xr = x + ((size_t)bb * NTOK + row * W0 + col) * DIM;
    float v0 = xr[tid], v1 = xr[tid + 256], v2 = xr[tid + 512];
    float mean = block_reduce_sum_256(v0 + v1 + v2) * (1.0f / DIM);
    float d0 = v0 - mean, d1 = v1 - mean, d2 = v2 - mean;
    float var = block_reduce_sum_256(d0 * d0 + d1 * d1 + d2 * d2) * (1.0f / DIM);
    float rs = rsqrtf(var + EPS);
    yr[tid]       = to_tf32(d0 * rs * g[tid]       + b[tid]);
    yr[tid + 256] = to_tf32(d1 * rs * g[tid + 256] + b[tid + 256]);
    yr[tid + 512] = to_tf32(d2 * rs * g[tid + 512] + b[tid + 512]);
}

// ---------------- plain LN (rows of 768; tf32-rounded out, feeds fc1) ----------------
__global__ void __launch_bounds__(256)
ln_kernel(const float* __restrict__ in,
          const float* __restrict__ g,
          const float* __restrict__ b,
          float* __restrict__ out) {
    size_t row = blockIdx.x;
    int tid = threadIdx.x;
    const float* xr = in + row * DIM;
    float v0 = xr[tid], v1 = xr[tid + 256], v2 = xr[tid + 512];
    float mean = block_reduce_sum_256(v0 + v1 + v2) * (1.0f / DIM);
    float d0 = v0 - mean, d1 = v1 - mean, d2 = v2 - mean;
    float var = block_reduce_sum_256(d0 * d0 + d1 * d1 + d2 * d2) * (1.0f / DIM);
    float rs = rsqrtf(var + EPS);
    float* yr = out + row * DIM;
    yr[tid]       = to_tf32(d0 * rs * g[tid]       + b[tid]);
    yr[tid + 256] = to_tf32(d1 * rs * g[tid + 256] + b[tid + 256]);
    yr[tid + 512] = to_tf32(d2 * rs * g[tid + 512] + b[tid + 512]);
}

// ---------------- cp.async helpers ----------------
__device__ __forceinline__ void cp_async16(uint32_t dst_smem, const void* src, int src_bytes) {
    asm volatile("cp.async.cg.shared.global [%0], [%1], 16, %2;\n"
                 :: "r"(dst_smem), "l"(src), "r"(src_bytes));
}
__device__ __forceinline__ void cp_commit() {
    asm volatile("cp.async.commit_group;\n" ::: "memory");
}
template <int N>
__device__ __forceinline__ void cp_wait() {
    asm volatile("cp.async.wait_group %0;\n" :: "n"(N) : "memory");
}

// ---------------- 128x128x16 tf32 GEMM, cp.async 4-stage pipeline ----------------
// Inputs A and W are PRE-ROUNDED to tf32 (producers/cvt kernel) — hot loop
// has zero cvt instructions.
// C[M,N] = A[M,K] * W[N,K]^T + bias. 256 threads = 8 warps (4x2), warp 32x64.
// tf32 m16n8k8 fragment layout (validated R4/R10):
//   A: a0=(g,t4) a1=(g+8,t4) a2=(g,t4+4) a3=(g+8,t4+4)
//   B: b0=(k=t4,n=g) b1=(k=t4+4,n=g)
//   C: c0=(g,2t4) c1=(g,2t4+1) c2=(g+8,2t4) c3=(g+8,2t4+1)
//  EPI 0: store C
//  EPI 1: window-revert scatter: C[pos] = extra[pos] + val (pad tokens dropped)
//  EPI 2: store exact GELU(val), tf32-rounded (feeds fc2)
//  EPI 3: store val + extra[m*N+n]
#define SPITCH 20
#define STAGEF (128 * SPITCH)          // floats per stage per matrix
#define GSMEM  (2 * 4 * STAGEF * 4)    // dyn smem bytes: 2 matrices x 4 stages

template <int EPI>
__global__ void __launch_bounds__(256, 2)
tgemm128(const float* __restrict__ A, const float* __restrict__ W,
         const float* __restrict__ bias, float* __restrict__ C,
         const float* __restrict__ extra, int M, int N, int K) {
    extern __shared__ float sm[];
    float* sA = sm;                    // [4][128][SPITCH]
    float* sB = sm + 4 * STAGEF;
    const uint32_t sA_u = (uint32_t)__cvta_generic_to_shared(sA);
    const uint32_t sB_u = (uint32_t)__cvta_generic_to_shared(sB);

    const int tid  = threadIdx.x;
    const int row0 = blockIdx.x * 128, col0 = blockIdx.y * 128;

    const int wid  = tid >> 5, lane = tid & 31;
    const int wm   = wid & 3, wn = wid >> 2;   // warp tile: rows wm*32, cols wn*64
    const int g    = lane >> 2, t4 = lane & 3;

    // loader mapping: quad q -> row q>>2, k-quad (q&3)*4
    const int r0q = tid >> 2,  k0q = (tid & 3) * 4;
    const int r1q = r0q + 64;
    const int a0row = row0 + r0q, a1row = row0 + r1q;
    const int a0b = (a0row < M) ? 16 : 0;
    const int a1b = (a1row < M) ? 16 : 0;
    const float* A0 = A + (size_t)(a0row < M ? a0row : M - 1) * K + k0q;
    const float* A1 = A + (size_t)(a1row < M ? a1row : M - 1) * K + k0q;
    const float* B0 = W + (size_t)(col0 + r0q) * K + k0q;
    const float* B1 = W + (size_t)(col0 + r1q) * K + k0q;
    const uint32_t dA0 = sA_u + (uint32_t)(r0q * SPITCH + k0q) * 4;
    const uint32_t dA1 = sA_u + (uint32_t)(r1q * SPITCH + k0q) * 4;
    const uint32_t dB0 = sB_u + (uint32_t)(r0q * SPITCH + k0q) * 4;
    const uint32_t dB1 = sB_u + (uint32_t)(r1q * SPITCH + k0q) * 4;
    const uint32_t stb = STAGEF * 4;   // stage stride in bytes

    float acc[2][8][4];
#pragma unroll
    for (int i = 0; i < 2; i++)
#pragma unroll
        for (int j = 0; j < 8; j++)
#pragma unroll
            for (int p = 0; p < 4; p++) acc[i][j][p] = 0.f;

    const int nt = K >> 4;

    // prologue: stages 0..2
#pragma unroll
    for (int s = 0; s < 3; s++) {
        const size_t ko = (size_t)s * 16;
        cp_async16(dA0 + s * stb, A0 + ko, a0b);
        cp_async16(dA1 + s * stb, A1 + ko, a1b);
        cp_async16(dB0 + s * stb, B0 + ko, 16);
        cp_async16(dB1 + s * stb, B1 + ko, 16);
        cp_commit();
    }

    for (int kt = 0; kt < nt; kt++) {
        cp_wait<2>();
        __syncthreads();
        const int st = (kt & 3) * STAGEF;
#pragma unroll
        for (int ks = 0; ks < 2; ks++) {
            const int k0 = ks * 8;
            float af[2][4], bf[8][2];
#pragma unroll
            for (int i = 0; i < 2; i++) {
                const int mrow = wm * 32 + i * 16 + g;
                af[i][0] = sA[st + mrow * SPITCH       + k0 + t4];
                af[i][1] = sA[st + (mrow + 8) * SPITCH + k0 + t4];
                af[i][2] = sA[st + mrow * SPITCH       + k0 + t4 + 4];
                af[i][3] = sA[st + (mrow + 8) * SPITCH + k0 + t4 + 4];
            }
#pragma unroll
            for (int j = 0; j < 8; j++) {
                const int nrow = wn * 64 + j * 8 + g;
                bf[j][0] = sB[st + nrow * SPITCH + k0 + t4];
                bf[j][1] = sB[st + nrow * SPITCH + k0 + t4 + 4];
            }
#pragma unroll
            for (int i = 0; i < 2; i++)
#pragma unroll
                for (int j = 0; j < 8; j++)
                    mma_tf32(acc[i][j], af[i], bf[j]);
        }
        if (kt + 3 < nt) {
            const int s = (kt + 3) & 3;
            const size_t ko = (size_t)(kt + 3) * 16;
            cp_async16(dA0 + s * stb, A0 + ko, a0b);
            cp_async16(dA1 + s * stb, A1 + ko, a1b);
            cp_async16(dB0 + s * stb, B0 + ko, 16);
            cp_async16(dB1 + s * stb, B1 + ko, 16);
        }
        cp_commit();
    }

    // ---------------- epilogue ----------------
    float bcol[8][2];
#pragma unroll
    for (int j = 0; j < 8; j++) {
        int c = col0 + wn * 64 + j * 8 + 2 * t4;
        bcol[j][0] = bias[c];
        bcol[j][1] = bias[c + 1];
    }
#pragma unroll
    for (int i = 0; i < 2; i++) {
#pragma unroll
        for (int r = 0; r < 2; r++) {
            int m = row0 + wm * 32 + i * 16 + r * 8 + g;
            if (m >= M) continue;
            if (EPI == 1) {
                int wi = m / NW, t = m - wi * NW;
                int bb = wi / NWIN_B;
                int wrem = wi - bb * NWIN_B;
                int wr = wrem / NWIN_D, wc = wrem - wr * NWIN_D;
                int rr = wr * WIN + t / WIN;
                int cc = wc * WIN + (t % WIN);
                if (rr < H0 && cc < W0) {
                    size_t ob = ((size_t)bb * NTOK + rr * W0 + cc) * DIM;
#pragma unroll
                    for (int j = 0; j < 8; j++) {
                        size_t o = ob + col0 + wn * 64 + j * 8 + 2 * t4;
                        float v0 = acc[i][j][r * 2]     + bcol[j][0] + extra[o];
                        float v1 = acc[i][j][r * 2 + 1] + bcol[j][1] + extra[o + 1];
                        *(float2*)&C[o] = make_float2(v0, v1);
                    }
                }
            } else {
                size_t ob = (size_t)m * N + col0 + wn * 64;
#pragma unroll
                for (int j = 0; j < 8; j++) {
                    size_t o = ob + j * 8 + 2 * t4;
                    float v0 = acc[i][j][r * 2]     + bcol[j][0];
                    float v1 = acc[i][j][r * 2 + 1] + bcol[j][1];
                    if (EPI == 2) {
                        v0 = to_tf32(0.5f * v0 * (1.0f + erff(v0 * 0.70710678118654752f)));
                        v1 = to_tf32(0.5f * v1 * (1.0f + erff(v1 * 0.70710678118654752f)));
                    } else if (EPI == 3) {
                        v0 += extra[o];
                        v1 += extra[o + 1];
                    }
                    *(float2*)&C[o] = make_float2(v0, v1);
                }
            }
        }
    }
}

// ---------------- windowed attention, one (window, head) per block ----------------
__global__ void __launch_bounds__(224)
attn_kernel(const float* __restrict__ qkv,
            const float* __restrict__ rel,
            float* __restrict__ outp) {
    extern __shared__ float smx[];
    float* sk = smx;
    float* sv = smx + NW * DH;
    int wi = blockIdx.x / HEADS;
    int h  = blockIdx.x - wi * HEADS;
    int tid = threadIdx.x;
    size_t base = (size_t)wi * NW * QKV_N + h * DH;
    for (int idx = tid; idx < NW * DH; idx += 224) {
        int t = idx >> 6, d = idx & 63;
        size_t o = base + (size_t)t * QKV_N + d;
        sk[idx] = qkv[o + DIM];
        sv[idx] = qkv[o + 2 * DIM];
    }
    __syncthreads();
    if (tid >= NW) return;

    float q[DH];
    {
        const float4* qp = (const float4*)(qkv + base + (size_t)tid * QKV_N);
#pragma unroll
        for (int i = 0; i < 16; i++) {
            float4 qq = qp[i];
            q[4 * i]     = qq.x * SCALE;
            q[4 * i + 1] = qq.y * SCALE;
            q[4 * i + 2] = qq.z * SCALE;
            q[4 * i + 3] = qq.w * SCALE;
        }
    }
    float acc[DH];
#pragma unroll
    for (int i = 0; i < DH; i++) acc[i] = 0.f;
    float mx = -1e30f, l = 0.f;
    const float* brow = rel + ((size_t)h * NW + tid) * NW;

    for (int j = 0; j < NW; j++) {
        const float4* kp = (const float4*)(sk + j * DH);
        float s = 0.f;
#pragma unroll
        for (int i = 0; i < 16; i++) {
            float4 kk = kp[i];
            s += q[4 * i] * kk.x + q[4 * i + 1] * kk.y
               + q[4 * i + 2] * kk.z + q[4 * i + 3] * kk.w;
        }
        s += brow[j];
        const float4* vp = (const float4*)(sv + j * DH);
        if (s <= mx) {
            float p = __expf(s - mx);
            l += p;
#pragma unroll
            for (int i = 0; i < 16; i++) {
                float4 vv = vp[i];
                acc[4 * i]     += p * vv.x;
                acc[4 * i + 1] += p * vv.y;
                acc[4 * i + 2] += p * vv.z;
                acc[4 * i + 3] += p * vv.w;
            }
        } else {
            float c = __expf(mx - s);
            l = l * c + 1.f;
            mx = s;
#pragma unroll
            for (int i = 0; i < 16; i++) {
                float4 vv = vp[i];
                acc[4 * i]     = acc[4 * i]     * c + vv.x;
                acc[4 * i + 1] = acc[4 * i + 1] * c + vv.y;
                acc[4 * i + 2] = acc[4 * i + 2] * c + vv.z;
                acc[4 * i + 3] = acc[4 * i + 3] * c + vv.w;
            }
        }
    }
    float inv = 1.0f / l;
    float4* op = (float4*)(outp + (size_t)(wi * NW + tid) * DIM + h * DH);
#pragma unroll
    for (int i = 0; i < 16; i++) {
        // tf32-round: feeds proj GEMM as A operand
        op[i] = make_float4(to_tf32(acc[4 * i] * inv), to_tf32(acc[4 * i + 1] * inv),
                            to_tf32(acc[4 * i + 2] * inv), to_tf32(acc[4 * i + 3] * inv));
    }
}

// ---------------- launcher ----------------
extern "C" void kernel_launch(void* const* d_in, const int* in_sizes, int n_in,
                              void* d_out, int out_size) {
    const float* x      = (const float*)d_in[0];
    const float* rel    = (const float*)d_in[1];
    const float* ln1_g  = (const float*)d_in[2];
    const float* ln1_b  = (const float*)d_in[3];
    const float* qkv_w  = (const float*)d_in[4];
    const float* qkv_b  = (const float*)d_in[5];
    const float* proj_w = (const float*)d_in[6];
    const float* proj_b = (const float*)d_in[7];
    const float* ln2_g  = (const float*)d_in[8];
    const float* ln2_b  = (const float*)d_in[9];
    const float* fc1_w  = (const float*)d_in[10];
    const float* fc1_b  = (const float*)d_in[11];
    const float* fc2_w  = (const float*)d_in[12];
    const float* fc2_b  = (const float*)d_in[13];
    float* out = (float*)d_out;

    float *p_xw, *p_qkv, *p_attnout, *p_x1, *p_ln2, *p_mlp;
    float *p_wq, *p_wp, *p_w1, *p_w2;
    cudaGetSymbolAddress((void**)&p_xw,      g_xw);
    cudaGetSymbolAddress((void**)&p_qkv,     g_qkv);
    cudaGetSymbolAddress((void**)&p_attnout, g_attnout);
    cudaGetSymbolAddress((void**)&p_x1,      g_x1);
    cudaGetSymbolAddress((void**)&p_ln2,     g_ln2);
    cudaGetSymbolAddress((void**)&p_mlp,     g_mlp);
    cudaGetSymbolAddress((void**)&p_wq,      g_wq);
    cudaGetSymbolAddress((void**)&p_wp,      g_wp);
    cudaGetSymbolAddress((void**)&p_w1,      g_w1);
    cudaGetSymbolAddress((void**)&p_w2,      g_w2);

    const int attn_smem = 2 * NW * DH * (int)sizeof(float);  // 100352 B
    cudaFuncSetAttribute(attn_kernel, cudaFuncAttributeMaxDynamicSharedMemorySize, attn_smem);
    cudaFuncSetAttribute(tgemm128<0>, cudaFuncAttributeMaxDynamicSharedMemorySize, GSMEM);
    cudaFuncSetAttribute(tgemm128<1>, cudaFuncAttributeMaxDynamicSharedMemorySize, GSMEM);
    cudaFuncSetAttribute(tgemm128<2>, cudaFuncAttributeMaxDynamicSharedMemorySize, GSMEM);
    cudaFuncSetAttribute(tgemm128<3>, cudaFuncAttributeMaxDynamicSharedMemorySize, GSMEM);

    // 0. tf32 pre-round the weights (cheap, overlaps nothing critical)
    {
        int nq = QKV_N * DIM, np = DIM * DIM, n1 = MLP_H * DIM, n2 = DIM * MLP_H;
        cvt_tf32_kernel<<<(nq / 4 + 255) / 256, 256>>>(qkv_w,  p_wq, nq);
        cvt_tf32_kernel<<<(np / 4 + 255) / 256, 256>>>(proj_w, p_wp, np);
        cvt_tf32_kernel<<<(n1 / 4 + 255) / 256, 256>>>(fc1_w,  p_w1, n1);
        cvt_tf32_kernel<<<(n2 / 4 + 255) / 256, 256>>>(fc2_w,  p_w2, n2);
    }

    // 1. LN1 + window partition (tf32-rounded out)
    ln1_window_kernel<<<MWIN, 256>>>(x, ln1_g, ln1_b, p_xw);

    // 2. QKV
    tgemm128<0><<<dim3((MWIN + 127) / 128, QKV_N / 128), 256, GSMEM>>>(
        p_xw, p_wq, qkv_b, p_qkv, nullptr, MWIN, QKV_N, DIM);

    // 3. Windowed attention (tf32-rounded out)
    attn_kernel<<<NWINTOT * HEADS, 224, attn_smem>>>(p_qkv, rel, p_attnout);

    // 4. Projection + window revert + residual
    tgemm128<1><<<dim3((MWIN + 127) / 128, DIM / 128), 256, GSMEM>>>(
        p_attnout, p_wp, proj_b, p_x1, x, MWIN, DIM, DIM);

    // 5. LN2 (tf32-rounded out)
    ln_kernel<<<MTOK, 256>>>(p_x1, ln2_g, ln2_b, p_ln2);

    // 6. fc1 + exact GELU (tf32-rounded out)
    tgemm128<2><<<dim3(MTOK / 128, MLP_H / 128), 256, GSMEM>>>(
        p_ln2, p_w1, fc1_b, p_mlp, nullptr, MTOK, MLP_H, DIM);

    // 7. fc2 + residual -> d_out
    tgemm128<3><<<dim3(MTOK / 128, DIM / 128), 256, GSMEM>>>(
        p_mlp, p_w2, fc2_b, out, p_x1, MTOK, DIM, MLP_H);
}

// round 15
// speedup vs baseline: 1.7807x; 1.0864x over previous
#include <cuda_runtime.h>
#include <math.h>
#include <stdint.h>

// ---------------- problem constants ----------------
#define DIM     768
#define HEADS   12
#define DH      64
#define WIN     14
#define NW      196          // WIN*WIN
#define BATCH   8
#define H0      64
#define W0      64
#define NTOK    4096         // H0*W0
#define NWIN_D  5            // windows per spatial dim (70/14)
#define NWIN_B  25           // windows per batch image
#define NWINTOT 200          // BATCH * NWIN_B
#define MWIN    (NWINTOT*NW) // 39200 windowed tokens
#define MTOK    (BATCH*NTOK) // 32768 real tokens
#define MLP_H   3072
#define QKV_N   (3*DIM)      // 2304
#define SCALE   0.125f
#define EPS     1e-5f

// ---------------- scratch (static device globals; no allocations) ----------------
__device__ float g_xw[(size_t)MWIN * DIM];
__device__ float g_qkv[(size_t)MWIN * QKV_N];
__device__ float g_attnout[(size_t)MWIN * DIM];
__device__ float g_x1[(size_t)MTOK * DIM];
__device__ float g_ln2[(size_t)MTOK * DIM];
__device__ float g_mlp[(size_t)MTOK * MLP_H];
// tf32-rounded weight copies
__device__ float g_wq[(size_t)QKV_N * DIM];
__device__ float g_wp[(size_t)DIM * DIM];
__device__ float g_w1[(size_t)MLP_H * DIM];
__device__ float g_w2[(size_t)DIM * MLP_H];

// ---------------- tf32 helpers ----------------
__device__ __forceinline__ float to_tf32(float x) {
    float r;
    asm("cvt.rna.tf32.f32 %0, %1;" : "=f"(r) : "f"(x));
    return r;
}
__device__ __forceinline__ void mma_tf32(float* c, const float* a, const float* b) {
    uint32_t a0 = __float_as_uint(a[0]), a1 = __float_as_uint(a[1]);
    uint32_t a2 = __float_as_uint(a[2]), a3 = __float_as_uint(a[3]);
    uint32_t b0 = __float_as_uint(b[0]), b1 = __float_as_uint(b[1]);
    asm volatile(
        "mma.sync.aligned.m16n8k8.row.col.f32.tf32.tf32.f32 "
        "{%0,%1,%2,%3}, {%4,%5,%6,%7}, {%8,%9}, {%0,%1,%2,%3};"
        : "+f"(c[0]), "+f"(c[1]), "+f"(c[2]), "+f"(c[3])
        : "r"(a0), "r"(a1), "r"(a2), "r"(a3), "r"(b0), "r"(b1));
}

// ---------------- weight tf32 pre-round (one-shot, idempotent) ----------------
__global__ void __launch_bounds__(256)
cvt_tf32_kernel(const float* __restrict__ in, float* __restrict__ out, int n) {
    int i = (blockIdx.x * 256 + threadIdx.x) * 4;
    if (i < n) {
        float4 v = *(const float4*)(in + i);
        v.x = to_tf32(v.x); v.y = to_tf32(v.y);
        v.z = to_tf32(v.z); v.w = to_tf32(v.w);
        *(float4*)(out + i) = v;
    }
}

// ---------------- block reduction ----------------
__device__ __forceinline__ float block_reduce_sum_256(float v) {
    __shared__ float red[8];
    int lane = threadIdx.x & 31, wid = threadIdx.x >> 5;
#pragma unroll
    for (int o = 16; o; o >>= 1) v += __shfl_xor_sync(0xffffffffu, v, o);
    __syncthreads();
    if (lane == 0) red[wid] = v;
    __syncthreads();
    float s = red[0];
#pragma unroll
    for (int i = 1; i < 8; i++) s += red[i];
    return s;
}

// ---------------- LN1 + window partition (pads -> zero rows; tf32-rounded out) ----------------
__global__ void __launch_bounds__(256)
ln1_window_kernel(const float* __restrict__ x,
                  const float* __restrict__ g,
                  const float* __restrict__ b,
                  float* __restrict__ y) {
    int wt = blockIdx.x;
    int wi = wt / NW, t = wt - wi * NW;
    int bb = wi / NWIN_B;
    int wrem = wi - bb * NWIN_B;
    int wr = wrem / NWIN_D, wc = wrem - wr * NWIN_D;
    int row = wr * WIN + t / WIN;
    int col = wc * WIN + (t % WIN);
    int tid = threadIdx.x;
    float* yr = y + (size_t)wt * DIM;
    if (row >= H0 || col >= W0) {
        yr[tid] = 0.f; yr[tid + 256] = 0.f; yr[tid + 512] = 0.f;
        return;
    }
    const float* xr = x + ((size_t)bb * NTOK + row * W0 + col) * DIM;
    float v0 = xr[tid], v1 = xr[tid + 256], v2 = xr[tid + 512];
    float mean = block_reduce_sum_256(v0 + v1 + v2) * (1.0f / DIM);
    float d0 = v0 - mean, d1 = v1 - mean, d2 = v2 - mean;
    float var = block_reduce_sum_256(d0 * d0 + d1 * d1 + d2 * d2) * (1.0f / DIM);
    float rs = rsqrtf(var + EPS);
    yr[tid]       = to_tf32(d0 * rs * g[tid]       + b[tid]);
    yr[tid + 256] = to_tf32(d1 * rs * g[tid + 256] + b[tid + 256]);
    yr[tid + 512] = to_tf32(d2 * rs * g[tid + 512] + b[tid + 512]);
}

// ---------------- plain LN (rows of 768; tf32-rounded out, feeds fc1) ----------------
__global__ void __launch_bounds__(256)
ln_kernel(const float* __restrict__ in,
          const float* __restrict__ g,
          const float* __restrict__ b,
          float* __restrict__ out) {
    size_t row = blockIdx.x;
    int tid = threadIdx.x;
    const float* xr = in + row * DIM;
    float v0 = xr[tid], v1 = xr[tid + 256], v2 = xr[tid + 512];
    float mean = block_reduce_sum_256(v0 + v1 + v2) * (1.0f / DIM);
    float d0 = v0 - mean, d1 = v1 - mean, d2 = v2 - mean;
    float var = block_reduce_sum_256(d0 * d0 + d1 * d1 + d2 * d2) * (1.0f / DIM);
    float rs = rsqrtf(var + EPS);
    float* yr = out + row * DIM;
    yr[tid]       = to_tf32(d0 * rs * g[tid]       + b[tid]);
    yr[tid + 256] = to_tf32(d1 * rs * g[tid + 256] + b[tid + 256]);
    yr[tid + 512] = to_tf32(d2 * rs * g[tid + 512] + b[tid + 512]);
}

// ---------------- cp.async helpers ----------------
__device__ __forceinline__ void cp_async16(uint32_t dst_smem, const void* src, int src_bytes) {
    asm volatile("cp.async.cg.shared.global [%0], [%1], 16, %2;\n"
                 :: "r"(dst_smem), "l"(src), "r"(src_bytes));
}
__device__ __forceinline__ void cp_commit() {
    asm volatile("cp.async.commit_group;\n" ::: "memory");
}
template <int N>
__device__ __forceinline__ void cp_wait() {
    asm volatile("cp.async.wait_group %0;\n" :: "n"(N) : "memory");
}

// ---------------- 128x128x32 tf32 GEMM, cp.async 3-stage pipeline ----------------
// k-tile 32: half the barrier/loop overhead of the k16 version.
// Inputs A and W are PRE-ROUNDED to tf32. 256 threads = 8 warps (4x2), warp 32x64.
// tf32 m16n8k8 fragment layout (validated R4/R10):
//   A: a0=(g,t4) a1=(g+8,t4) a2=(g,t4+4) a3=(g+8,t4+4)
//   B: b0=(k=t4,n=g) b1=(k=t4+4,n=g)
//   C: c0=(g,2t4) c1=(g,2t4+1) c2=(g+8,2t4) c3=(g+8,2t4+1)
//  EPI 0: store C
//  EPI 1: window-revert scatter: C[pos] = extra[pos] + val (pad tokens dropped)
//  EPI 2: store exact GELU(val), tf32-rounded (feeds fc2)
//  EPI 3: store val + extra[m*N+n]
#define SPITCH 36
#define STAGEF (128 * SPITCH)          // floats per stage per matrix (4608)
#define NSTAGE 3
#define GSMEM  (2 * NSTAGE * STAGEF * 4)   // 110592 B

template <int EPI>
__global__ void __launch_bounds__(256, 2)
tgemm128(const float* __restrict__ A, const float* __restrict__ W,
         const float* __restrict__ bias, float* __restrict__ C,
         const float* __restrict__ extra, int M, int N, int K) {
    extern __shared__ float sm[];
    float* sA = sm;                    // [NSTAGE][128][SPITCH]
    float* sB = sm + NSTAGE * STAGEF;
    const uint32_t sA_u = (uint32_t)__cvta_generic_to_shared(sA);
    const uint32_t sB_u = (uint32_t)__cvta_generic_to_shared(sB);

    const int tid  = threadIdx.x;
    const int row0 = blockIdx.x * 128, col0 = blockIdx.y * 128;

    const int wid  = tid >> 5, lane = tid & 31;
    const int wm   = wid & 3, wn = wid >> 2;   // warp tile: rows wm*32, cols wn*64
    const int g    = lane >> 2, t4 = lane & 3;

    // loader mapping for k32 stages: 1024 quads/matrix-stage, 4 per thread.
    // quad q = tid + i*256 -> row (tid>>3)+32i, k-quad (tid&7)*4 (same for all i)
    const int rq = tid >> 3;
    const int kq = (tid & 7) * 4;
    int   ab[4];
    const float* Aq[4];
    const float* Bq[4];
    uint32_t dAq[4], dBq[4];
#pragma unroll
    for (int i = 0; i < 4; i++) {
        const int r = rq + 32 * i;
        const int arow = row0 + r;
        ab[i] = (arow < M) ? 16 : 0;
        Aq[i] = A + (size_t)(arow < M ? arow : M - 1) * K + kq;
        Bq[i] = W + (size_t)(col0 + r) * K + kq;
        dAq[i] = sA_u + (uint32_t)(r * SPITCH + kq) * 4;
        dBq[i] = sB_u + (uint32_t)(r * SPITCH + kq) * 4;
    }
    const uint32_t stb = STAGEF * 4;   // stage stride in bytes

    float acc[2][8][4];
#pragma unroll
    for (int i = 0; i < 2; i++)
#pragma unroll
        for (int j = 0; j < 8; j++)
#pragma unroll
            for (int p = 0; p < 4; p++) acc[i][j][p] = 0.f;

    const int nt = K >> 5;             // k32 tiles

    // prologue: stages 0,1
#pragma unroll
    for (int s = 0; s < 2; s++) {
        const size_t ko = (size_t)s * 32;
#pragma unroll
        for (int i = 0; i < 4; i++) {
            cp_async16(dAq[i] + s * stb, Aq[i] + ko, ab[i]);
            cp_async16(dBq[i] + s * stb, Bq[i] + ko, 16);
        }
        cp_commit();
    }

    int stage = 0;      // buffer holding tile kt
    int istage = 2;     // buffer to fill with tile kt+2
    for (int kt = 0; kt < nt; kt++) {
        cp_wait<1>();          // stage kt complete
        __syncthreads();
        const int st = stage * STAGEF;
#pragma unroll
        for (int ks = 0; ks < 4; ks++) {
            const int k0 = ks * 8;
            float af[2][4], bf[8][2];
#pragma unroll
            for (int i = 0; i < 2; i++) {
                const int mrow = wm * 32 + i * 16 + g;
                af[i][0] = sA[st + mrow * SPITCH       + k0 + t4];
                af[i][1] = sA[st + (mrow + 8) * SPITCH + k0 + t4];
                af[i][2] = sA[st + mrow * SPITCH       + k0 + t4 + 4];
                af[i][3] = sA[st + (mrow + 8) * SPITCH + k0 + t4 + 4];
            }
#pragma unroll
            for (int j = 0; j < 8; j++) {
                const int nrow = wn * 64 + j * 8 + g;
                bf[j][0] = sB[st + nrow * SPITCH + k0 + t4];
                bf[j][1] = sB[st + nrow * SPITCH + k0 + t4 + 4];
            }
#pragma unroll
            for (int i = 0; i < 2; i++)
#pragma unroll
                for (int j = 0; j < 8; j++)
                    mma_tf32(acc[i][j], af[i], bf[j]);
        }
        // fill stage kt+2 (its buffer was consumed at kt-1; safe after sync)
        if (kt + 2 < nt) {
            const size_t ko = (size_t)(kt + 2) * 32;
            const uint32_t so = istage * stb;
#pragma unroll
            for (int i = 0; i < 4; i++) {
                cp_async16(dAq[i] + so, Aq[i] + ko, ab[i]);
                cp_async16(dBq[i] + so, Bq[i] + ko, 16);
            }
        }
        cp_commit();
        stage  = (stage  == NSTAGE - 1) ? 0 : stage + 1;
        istage = (istage == NSTAGE - 1) ? 0 : istage + 1;
    }

    // ---------------- epilogue ----------------
    float bcol[8][2];
#pragma unroll
    for (int j = 0; j < 8; j++) {
        int c = col0 + wn * 64 + j * 8 + 2 * t4;
        bcol[j][0] = bias[c];
        bcol[j][1] = bias[c + 1];
    }
#pragma unroll
    for (int i = 0; i < 2; i++) {
#pragma unroll
        for (int r = 0; r < 2; r++) {
            int m = row0 + wm * 32 + i * 16 + r * 8 + g;
            if (m >= M) continue;
            if (EPI == 1) {
                int wi = m / NW, t = m - wi * NW;
                int bb = wi / NWIN_B;
                int wrem = wi - bb * NWIN_B;
                int wr = wrem / NWIN_D, wc = wrem - wr * NWIN_D;
                int rr = wr * WIN + t / WIN;
                int cc = wc * WIN + (t % WIN);
                if (rr < H0 && cc < W0) {
                    size_t ob = ((size_t)bb * NTOK + rr * W0 + cc) * DIM;
#pragma unroll
                    for (int j = 0; j < 8; j++) {
                        size_t o = ob + col0 + wn * 64 + j * 8 + 2 * t4;
                        float v0 = acc[i][j][r * 2]     + bcol[j][0] + extra[o];
                        float v1 = acc[i][j][r * 2 + 1] + bcol[j][1] + extra[o + 1];
                        *(float2*)&C[o] = make_float2(v0, v1);
                    }
                }
            } else {
                size_t ob = (size_t)m * N + col0 + wn * 64;
#pragma unroll
                for (int j = 0; j < 8; j++) {
                    size_t o = ob + j * 8 + 2 * t4;
                    float v0 = acc[i][j][r * 2]     + bcol[j][0];
                    float v1 = acc[i][j][r * 2 + 1] + bcol[j][1];
                    if (EPI == 2) {
                        v0 = to_tf32(0.5f * v0 * (1.0f + erff(v0 * 0.70710678118654752f)));
                        v1 = to_tf32(0.5f * v1 * (1.0f + erff(v1 * 0.70710678118654752f)));
                    } else if (EPI == 3) {
                        v0 += extra[o];
                        v1 += extra[o + 1];
                    }
                    *(float2*)&C[o] = make_float2(v0, v1);
                }
            }
        }
    }
}

// ---------------- windowed attention, one (window, head) per block ----------------
__global__ void __launch_bounds__(224)
attn_kernel(const float* __restrict__ qkv,
            const float* __restrict__ rel,
            float* __restrict__ outp) {
    extern __shared__ float smx[];
    float* sk = smx;
    float* sv = smx + NW * DH;
    int wi = blockIdx.x / HEADS;
    int h  = blockIdx.x - wi * HEADS;
    int tid = threadIdx.x;
    size_t base = (size_t)wi * NW * QKV_N + h * DH;
    for (int idx = tid; idx < NW * DH; idx += 224) {
        int t = idx >> 6, d = idx & 63;
        size_t o = base + (size_t)t * QKV_N + d;
        sk[idx] = qkv[o + DIM];
        sv[idx] = qkv[o + 2 * DIM];
    }
    __syncthreads();
    if (tid >= NW) return;

    float q[DH];
    {
        const float4* qp = (const float4*)(qkv + base + (size_t)tid * QKV_N);
#pragma unroll
        for (int i = 0; i < 16; i++) {
            float4 qq = qp[i];
            q[4 * i]     = qq.x * SCALE;
            q[4 * i + 1] = qq.y * SCALE;
            q[4 * i + 2] = qq.z * SCALE;
            q[4 * i + 3] = qq.w * SCALE;
        }
    }
    float acc[DH];
#pragma unroll
    for (int i = 0; i < DH; i++) acc[i] = 0.f;
    float mx = -1e30f, l = 0.f;
    const float* brow = rel + ((size_t)h * NW + tid) * NW;

    for (int j = 0; j < NW; j++) {
        const float4* kp = (const float4*)(sk + j * DH);
        float s = 0.f;
#pragma unroll
        for (int i = 0; i < 16; i++) {
            float4 kk = kp[i];
            s += q[4 * i] * kk.x + q[4 * i + 1] * kk.y
               + q[4 * i + 2] * kk.z + q[4 * i + 3] * kk.w;
        }
        s += brow[j];
        const float4* vp = (const float4*)(sv + j * DH);
        if (s <= mx) {
            float p = __expf(s - mx);
            l += p;
#pragma unroll
            for (int i = 0; i < 16; i++) {
                float4 vv = vp[i];
                acc[4 * i]     += p * vv.x;
                acc[4 * i + 1] += p * vv.y;
                acc[4 * i + 2] += p * vv.z;
                acc[4 * i + 3] += p * vv.w;
            }
        } else {
            float c = __expf(mx - s);
            l = l * c + 1.f;
            mx = s;
#pragma unroll
            for (int i = 0; i < 16; i++) {
                float4 vv = vp[i];
                acc[4 * i]     = acc[4 * i]     * c + vv.x;
                acc[4 * i + 1] = acc[4 * i + 1] * c + vv.y;
                acc[4 * i + 2] = acc[4 * i + 2] * c + vv.z;
                acc[4 * i + 3] = acc[4 * i + 3] * c + vv.w;
            }
        }
    }
    float inv = 1.0f / l;
    float4* op = (float4*)(outp + (size_t)(wi * NW + tid) * DIM + h * DH);
#pragma unroll
    for (int i = 0; i < 16; i++) {
        op[i] = make_float4(to_tf32(acc[4 * i] * inv), to_tf32(acc[4 * i + 1] * inv),
                            to_tf32(acc[4 * i + 2] * inv), to_tf32(acc[4 * i + 3] * inv));
    }
}

// ---------------- launcher ----------------
extern "C" void kernel_launch(void* const* d_in, const int* in_sizes, int n_in,
                              void* d_out, int out_size) {
    const float* x      = (const float*)d_in[0];
    const float* rel    = (const float*)d_in[1];
    const float* ln1_g  = (const float*)d_in[2];
    const float* ln1_b  = (const float*)d_in[3];
    const float* qkv_w  = (const float*)d_in[4];
    const float* qkv_b  = (const float*)d_in[5];
    const float* proj_w = (const float*)d_in[6];
    const float* proj_b = (const float*)d_in[7];
    const float* ln2_g  = (const float*)d_in[8];
    const float* ln2_b  = (const float*)d_in[9];
    const float* fc1_w  = (const float*)d_in[10];
    const float* fc1_b  = (const float*)d_in[11];
    const float* fc2_w  = (const float*)d_in[12];
    const float* fc2_b  = (const float*)d_in[13];
    float* out = (float*)d_out;

    float *p_xw, *p_qkv, *p_attnout, *p_x1, *p_ln2, *p_mlp;
    float *p_wq, *p_wp, *p_w1, *p_w2;
    cudaGetSymbolAddress((void**)&p_xw,      g_xw);
    cudaGetSymbolAddress((void**)&p_qkv,     g_qkv);
    cudaGetSymbolAddress((void**)&p_attnout, g_attnout);
    cudaGetSymbolAddress((void**)&p_x1,      g_x1);
    cudaGetSymbolAddress((void**)&p_ln2,     g_ln2);
    cudaGetSymbolAddress((void**)&p_mlp,     g_mlp);
    cudaGetSymbolAddress((void**)&p_wq,      g_wq);
    cudaGetSymbolAddress((void**)&p_wp,      g_wp);
    cudaGetSymbolAddress((void**)&p_w1,      g_w1);
    cudaGetSymbolAddress((void**)&p_w2,      g_w2);

    const int attn_smem = 2 * NW * DH * (int)sizeof(float);  // 100352 B
    cudaFuncSetAttribute(attn_kernel, cudaFuncAttributeMaxDynamicSharedMemorySize, attn_smem);
    cudaFuncSetAttribute(tgemm128<0>, cudaFuncAttributeMaxDynamicSharedMemorySize, GSMEM);
    cudaFuncSetAttribute(tgemm128<1>, cudaFuncAttributeMaxDynamicSharedMemorySize, GSMEM);
    cudaFuncSetAttribute(tgemm128<2>, cudaFuncAttributeMaxDynamicSharedMemorySize, GSMEM);
    cudaFuncSetAttribute(tgemm128<3>, cudaFuncAttributeMaxDynamicSharedMemorySize, GSMEM);

    // 0. tf32 pre-round the weights
    {
        int nq = QKV_N * DIM, np = DIM * DIM, n1 = MLP_H * DIM, n2 = DIM * MLP_H;
        cvt_tf32_kernel<<<(nq / 4 + 255) / 256, 256>>>(qkv_w,  p_wq, nq);
        cvt_tf32_kernel<<<(np / 4 + 255) / 256, 256>>>(proj_w, p_wp, np);
        cvt_tf32_kernel<<<(n1 / 4 + 255) / 256, 256>>>(fc1_w,  p_w1, n1);
        cvt_tf32_kernel<<<(n2 / 4 + 255) / 256, 256>>>(fc2_w,  p_w2, n2);
    }

    // 1. LN1 + window partition (tf32-rounded out)
    ln1_window_kernel<<<MWIN, 256>>>(x, ln1_g, ln1_b, p_xw);

    // 2. QKV
    tgemm128<0><<<dim3((MWIN + 127) / 128, QKV_N / 128), 256, GSMEM>>>(
        p_xw, p_wq, qkv_b, p_qkv, nullptr, MWIN, QKV_N, DIM);

    // 3. Windowed attention (tf32-rounded out)
    attn_kernel<<<NWINTOT * HEADS, 224, attn_smem>>>(p_qkv, rel, p_attnout);

    // 4. Projection + window revert + residual
    tgemm128<1><<<dim3((MWIN + 127) / 128, DIM / 128), 256, GSMEM>>>(
        p_attnout, p_wp, proj_b, p_x1, x, MWIN, DIM, DIM);

    // 5. LN2 (tf32-rounded out)
    ln_kernel<<<MTOK, 256>>>(p_x1, ln2_g, ln2_b, p_ln2);

    // 6. fc1 + exact GELU (tf32-rounded out)
    tgemm128<2><<<dim3(MTOK / 128, MLP_H / 128), 256, GSMEM>>>(
        p_ln2, p_w1, fc1_b, p_mlp, nullptr, MTOK, MLP_H, DIM);

    // 7. fc2 + residual -> d_out
    tgemm128<3><<<dim3(MTOK / 128, DIM / 128), 256, GSMEM>>>(
        p_mlp, p_w2, fc2_b, out, p_x1, MTOK, DIM, MLP_H);
}